// round 13
// baseline (speedup 1.0000x reference)
#include <cuda_runtime.h>
#include <cuda_bf16.h>
#include <math.h>
#include <stdint.h>

#define Bb     256
#define Tt     512
#define Dd     128
#define Hh     256
#define H2     512
#define Ee     64
#define BT     (Bb * Tt)          // 131072
#define BETAc  0.9f
#define THRc   1.0f
#define RSCALEc 0.25f
#define EPSc   1e-5f

#define WREC_CACHED 224           // rows of W_rec cached in smem (224KB)
#define SCAN_SMEM  (WREC_CACHED * Hh * 4)

// ---------------- scratch (device globals; no allocation allowed) ----------------
__device__ float         g_nx[BT * Dd];       // normalized input (exact R4 bits)
__device__ float         g_curin[BT * Hh];    // input currents
__device__ __nv_bfloat16 g_spkb[BT * Hh];     // spike trace (bf16, exact 0/1)
__device__ __nv_bfloat16 g_mh[BT * Hh];       // membrane hi bf16
__device__ __nv_bfloat16 g_ml[BT * Hh];       // membrane lo bf16
__device__ float         g_stats[BT * 2];     // per-row mu, rstd for LN2
__device__ __nv_bfloat16 g_gh[BT * Hh];       // gmid hi bf16
__device__ __nv_bfloat16 g_gl[BT * Hh];       // gmid lo bf16
__device__ float         g_pooled[Bb * H2];   // [spike mean | last mem (exact fp32)]
__device__ float         g_bias1[Hh];         // bd1 + ln2_b @ Wd1
__device__ float         g_cols[Hh];          // colsum of g*Wd1
__device__ __nv_bfloat16 g_W1h[Hh * H2];      // (g*Wd1)^T hi  [N=256][K=512]
__device__ __nv_bfloat16 g_W1l[Hh * H2];
__device__ __nv_bfloat16 g_W2h[Dd * Hh];      // Wd2^T hi      [N=128][K=256]
__device__ __nv_bfloat16 g_W2l[Dd * Hh];

// ---------------- helpers ----------------
__device__ __forceinline__ float gelu_exact(float v) {
    return 0.5f * v * (1.0f + erff(v * 0.70710678118654752440f));
}
__device__ __forceinline__ uint32_t smem_u32(const void* p) {
    uint32_t a;
    asm("{ .reg .u64 t; cvta.to.shared.u64 t, %1; cvt.u32.u64 %0, t; }" : "=r"(a) : "l"(p));
    return a;
}
__device__ __forceinline__ float blockReduceSum(float v, float* sh) {
    int lane = threadIdx.x & 31, w = threadIdx.x >> 5;
    #pragma unroll
    for (int o = 16; o; o >>= 1) v += __shfl_down_sync(0xffffffffu, v, o);
    if (lane == 0) sh[w] = v;
    __syncthreads();
    int nw = blockDim.x >> 5;
    v = (threadIdx.x < nw) ? sh[threadIdx.x] : 0.0f;
    if (w == 0) {
        #pragma unroll
        for (int o = 16; o; o >>= 1) v += __shfl_down_sync(0xffffffffu, v, o);
        if (lane == 0) sh[0] = v;
    }
    __syncthreads();
    float r = sh[0];
    __syncthreads();
    return r;
}
__device__ __forceinline__ void splitf(float x, float& hi, float& lo) {
    __nv_bfloat16 b = __float2bfloat16(x);
    hi = __bfloat162float(b);
    lo = x - hi;
}
__device__ __forceinline__ uint32_t packbf(float x0, float x1) {
    uint32_t l = __bfloat16_as_ushort(__float2bfloat16(x0));
    uint32_t h = __bfloat16_as_ushort(__float2bfloat16(x1));
    return l | (h << 16);
}

#define LDSM4(r, addr) \
    asm volatile("ldmatrix.sync.aligned.m8n8.x4.shared.b16 {%0,%1,%2,%3}, [%4];" \
        : "=r"((r)[0]), "=r"((r)[1]), "=r"((r)[2]), "=r"((r)[3]) : "r"(addr))

#define MMA_BF16(d, a, b) \
    asm volatile("mma.sync.aligned.m16n8k16.row.col.f32.bf16.bf16.f32 " \
        "{%0,%1,%2,%3}, {%4,%5,%6,%7}, {%8,%9}, {%0,%1,%2,%3};" \
        : "+f"((d)[0]), "+f"((d)[1]), "+f"((d)[2]), "+f"((d)[3]) \
        : "r"((a)[0]), "r"((a)[1]), "r"((a)[2]), "r"((a)[3]), "r"((b)[0]), "r"((b)[1]))

#define CP_ASYNC16(dst, src) \
    asm volatile("cp.async.cg.shared.global [%0], [%1], 16;" :: "r"(dst), "l"(src))
#define CP_COMMIT() asm volatile("cp.async.commit_group;" ::: "memory")
#define CP_WAIT0()  asm volatile("cp.async.wait_group 0;" ::: "memory")
#define CP_WAIT1()  asm volatile("cp.async.wait_group 1;" ::: "memory")

// ---------------- kernel 1: LayerNorm over D=128 (EXACT R4 bits) ----------------
__global__ void ln1_kernel(const float* __restrict__ x,
                           const float* __restrict__ g,
                           const float* __restrict__ b) {
    __shared__ float sh[32];
    int m = blockIdx.x;
    float v = x[m * Dd + threadIdx.x];
    float mu = blockReduceSum(v, sh) * (1.0f / Dd);
    float d = v - mu;
    float var = blockReduceSum(d * d, sh) * (1.0f / Dd);
    g_nx[m * Dd + threadIdx.x] = d * rsqrtf(var + EPSc) * g[threadIdx.x] + b[threadIdx.x];
}

// ---------------- kernel 2: cur_in fp32 SIMT GEMM, pipelined (EXACT R4 FP order) ----------------
// PINNED: curin numerics must stay this exact fp32 bit-path (R6/R7/R12 forensics).
__global__ void __launch_bounds__(256)
curin_gemm(const float* __restrict__ mask,
           const float* __restrict__ W_in,
           const float* __restrict__ b_in,
           const float* __restrict__ W_mask) {
    __shared__ __align__(16) float As[2][16][132];
    __shared__ __align__(16) float Bs[2][16][132];
    int m0 = blockIdx.y * 128, n0 = blockIdx.x * 128;
    int tid = threadIdx.x, ty = tid >> 4, tx = tid & 15;
    float acc[8][8];
    #pragma unroll
    for (int i = 0; i < 8; i++)
        #pragma unroll
        for (int j = 0; j < 8; j++) acc[i][j] = 0.0f;

    float4 rA[2];
    auto loadA = [&](int c, float4* r) {
        const float* A = (c < 8) ? (const float*)g_nx : mask;
        int k0 = (c & 7) * 16;
        #pragma unroll
        for (int rep = 0; rep < 2; rep++) {
            int e = tid + rep * 256;
            int rr = e >> 2, c4 = (e & 3) * 4;
            r[rep] = *reinterpret_cast<const float4*>(A + (size_t)(m0 + rr) * Dd + k0 + c4);
        }
    };
    auto stsA = [&](int s, const float4* r) {
        #pragma unroll
        for (int rep = 0; rep < 2; rep++) {
            int e = tid + rep * 256;
            int rr = e >> 2, c4 = (e & 3) * 4;
            As[s][c4 + 0][rr] = r[rep].x; As[s][c4 + 1][rr] = r[rep].y;
            As[s][c4 + 2][rr] = r[rep].z; As[s][c4 + 3][rr] = r[rep].w;
        }
    };
    auto issueB = [&](int c) {
        const float* Bm = (c < 8) ? W_in : W_mask;
        int k0 = (c & 7) * 16, s = c & 1;
        #pragma unroll
        for (int rep = 0; rep < 2; rep++) {
            int e = tid + rep * 256;
            int rr = e >> 5, cc = (e & 31) * 4;
            CP_ASYNC16(smem_u32(&Bs[s][rr][cc]),
                       Bm + (size_t)(k0 + rr) * Hh + n0 + cc);
        }
        CP_COMMIT();
    };

    loadA(0, rA); issueB(0); stsA(0, rA);
    loadA(1, rA); issueB(1);

    for (int c = 0; c < 16; c++) {
        int s = c & 1;
        if (c + 1 < 16) CP_WAIT1(); else CP_WAIT0();
        __syncthreads();
        #pragma unroll
        for (int k = 0; k < 16; k++) {
            float4 a0 = *reinterpret_cast<const float4*>(&As[s][k][ty * 8]);
            float4 a1 = *reinterpret_cast<const float4*>(&As[s][k][ty * 8 + 4]);
            float4 b0 = *reinterpret_cast<const float4*>(&Bs[s][k][tx * 8]);
            float4 b1 = *reinterpret_cast<const float4*>(&Bs[s][k][tx * 8 + 4]);
            float av[8] = {a0.x, a0.y, a0.z, a0.w, a1.x, a1.y, a1.z, a1.w};
            float bv[8] = {b0.x, b0.y, b0.z, b0.w, b1.x, b1.y, b1.z, b1.w};
            #pragma unroll
            for (int i = 0; i < 8; i++)
                #pragma unroll
                for (int j = 0; j < 8; j++) acc[i][j] += av[i] * bv[j];
        }
        __syncthreads();
        if (c + 1 < 16) stsA(s ^ 1, rA);
        if (c + 2 < 16) { loadA(c + 2, rA); issueB(c + 2); }
    }
    #pragma unroll
    for (int i = 0; i < 8; i++) {
        int m = m0 + ty * 8 + i;
        #pragma unroll
        for (int j = 0; j < 8; j++) {
            int n = n0 + tx * 8 + j;
            g_curin[(size_t)m * Hh + n] = acc[i][j] + b_in[n];
        }
    }
}

// ---------------- kernel 3: scan with W_rec smem cache (bit-identical add order) ----------------
__global__ void __launch_bounds__(256)
scan_kernel(const float* __restrict__ Wrec) {
    extern __shared__ __align__(16) float sW[];   // [WREC_CACHED][Hh]
    __shared__ unsigned char list[Hh];
    __shared__ int warpcnt[8];
    int b = blockIdx.x;
    int h = threadIdx.x;
    int lane = h & 31, w = h >> 5;

    // cache rows [0, WREC_CACHED) of W_rec (identical bits; source change only)
    for (int i = h; i < WREC_CACHED * Hh / 4; i += 256)
        reinterpret_cast<float4*>(sW)[i] = reinterpret_cast<const float4*>(Wrec)[i];
    __syncthreads();

    float mem = 0.0f, spksum = 0.0f;
    int prev = 0;
    const float* cbase = g_curin + (size_t)b * Tt * Hh + h;
    __nv_bfloat16* sbase = g_spkb + (size_t)b * Tt * Hh + h;
    __nv_bfloat16* mhb = g_mh + (size_t)b * Tt * Hh + h;
    __nv_bfloat16* mlb = g_ml + (size_t)b * Tt * Hh + h;

    auto wload = [&](int r) -> float {
        return (r < WREC_CACHED) ? sW[r * Hh + h] : Wrec[r * Hh + h];
    };

    float cur_next = cbase[0];
    for (int t = 0; t < Tt; t++) {
        unsigned bal = __ballot_sync(0xffffffffu, prev);
        if (lane == 0) warpcnt[w] = __popc(bal);
        __syncthreads();
        int base = 0, ntot = 0;
        #pragma unroll
        for (int i = 0; i < 8; i++) {
            int c = warpcnt[i];
            if (i < w) base += c;
            ntot += c;
        }
        if (prev) list[base + __popc(bal & ((1u << lane) - 1u))] = (unsigned char)h;
        __syncthreads();

        float cin = cur_next;
        if (t + 1 < Tt) cur_next = cbase[(size_t)(t + 1) * Hh];

        float rec = 0.0f;
        int j = 0;
        for (; j + 8 <= ntot; j += 8) {
            float v0 = wload((int)list[j]);
            float v1 = wload((int)list[j + 1]);
            float v2 = wload((int)list[j + 2]);
            float v3 = wload((int)list[j + 3]);
            float v4 = wload((int)list[j + 4]);
            float v5 = wload((int)list[j + 5]);
            float v6 = wload((int)list[j + 6]);
            float v7 = wload((int)list[j + 7]);
            rec += v0; rec += v1; rec += v2; rec += v3;
            rec += v4; rec += v5; rec += v6; rec += v7;
        }
        for (; j + 4 <= ntot; j += 4) {
            float v0 = wload((int)list[j]);
            float v1 = wload((int)list[j + 1]);
            float v2 = wload((int)list[j + 2]);
            float v3 = wload((int)list[j + 3]);
            rec += v0; rec += v1; rec += v2; rec += v3;
        }
        for (; j < ntot; j++) rec += wload((int)list[j]);

        float cur = cin + rec * RSCALEc;
        mem = BETAc * mem + cur;
        float s = (mem - THRc >= 0.0f) ? 1.0f : 0.0f;
        mem -= s * THRc;
        sbase[(size_t)t * Hh] = __float2bfloat16(s);
        float hi, lo; splitf(mem, hi, lo);
        mhb[(size_t)t * Hh] = __float2bfloat16(hi);
        mlb[(size_t)t * Hh] = __float2bfloat16(lo);
        spksum += s;
        prev = (s != 0.0f);
    }
    g_pooled[b * H2 + h]      = spksum * (1.0f / Tt);
    g_pooled[b * H2 + Hh + h] = mem;
}

// ---------------- kernel 4: per-row LN2 stats, warp per row ----------------
__global__ void rowstats_kernel() {
    int row = blockIdx.x * 8 + (threadIdx.x >> 5);
    int lane = threadIdx.x & 31;
    uint4 a  = *reinterpret_cast<const uint4*>(g_spkb + (size_t)row * Hh + lane * 8);
    uint4 m1 = *reinterpret_cast<const uint4*>(g_mh   + (size_t)row * Hh + lane * 8);
    uint4 m2 = *reinterpret_cast<const uint4*>(g_ml   + (size_t)row * Hh + lane * 8);
    float s = 0.0f, q = 0.0f;
    uint32_t ws[4] = {a.x, a.y, a.z, a.w};
    uint32_t wh[4] = {m1.x, m1.y, m1.z, m1.w};
    uint32_t wl[4] = {m2.x, m2.y, m2.z, m2.w};
    #pragma unroll
    for (int i = 0; i < 4; i++) {
        __nv_bfloat162 p = *reinterpret_cast<__nv_bfloat162*>(&ws[i]);
        float v0 = __low2float(p), v1 = __high2float(p);
        s += v0 + v1;
        q += v0 * v0 + v1 * v1;
        __nv_bfloat162 ph = *reinterpret_cast<__nv_bfloat162*>(&wh[i]);
        __nv_bfloat162 pl = *reinterpret_cast<__nv_bfloat162*>(&wl[i]);
        float c0 = __low2float(ph) + __low2float(pl);
        float c1 = __high2float(ph) + __high2float(pl);
        s += c0 + c1;
        q += c0 * c0 + c1 * c1;
    }
    #pragma unroll
    for (int o = 16; o; o >>= 1) {
        s += __shfl_down_sync(0xffffffffu, s, o);
        q += __shfl_down_sync(0xffffffffu, q, o);
    }
    if (lane == 0) {
        float mu = s * (1.0f / H2);
        float var = q * (1.0f / H2) - mu * mu;
        g_stats[row * 2]     = mu;
        g_stats[row * 2 + 1] = rsqrtf(var + EPSc);
    }
}

// ---------------- prep kernels for decoder weights ----------------
__global__ void prep_w1(const float* __restrict__ ln2g, const float* __restrict__ ln2b,
                        const float* __restrict__ Wd1, const float* __restrict__ bd1) {
    __shared__ float sh[32];
    int n = blockIdx.x, tid = threadIdx.x;
    float cs = 0.0f, bs = 0.0f;
    for (int k = tid; k < H2; k += 128) {
        float wraw = Wd1[k * Hh + n];
        float w = ln2g[k] * wraw;
        float hi, lo; splitf(w, hi, lo);
        g_W1h[n * H2 + k] = __float2bfloat16(hi);
        g_W1l[n * H2 + k] = __float2bfloat16(lo);
        cs += w;
        bs += ln2b[k] * wraw;
    }
    cs = blockReduceSum(cs, sh);
    bs = blockReduceSum(bs, sh);
    if (tid == 0) { g_cols[n] = cs; g_bias1[n] = bd1[n] + bs; }
}
__global__ void prep_w2(const float* __restrict__ Wd2) {
    int n = blockIdx.x, k = threadIdx.x;
    float w = Wd2[k * Dd + n];
    float hi, lo; splitf(w, hi, lo);
    g_W2h[n * Hh + k] = __float2bfloat16(hi);
    g_W2l[n * Hh + k] = __float2bfloat16(lo);
}

// =====================================================================
// mma.sync bf16 split GEMM (decoder), cp.async double-buffered (R9 proven).
// =====================================================================
#define MG_SMEM (2 * 4 * 128 * 72 * 2)   // 147456 bytes

template <int KTOT, bool DEC1>
__global__ void __launch_bounds__(256)
mma_gemm(const float* __restrict__ biasP, float* __restrict__ outP) {
    extern __shared__ __align__(16) __nv_bfloat16 smb[];
    const int tid = threadIdx.x, lane = tid & 31, wid = tid >> 5;
    const int wm = wid & 3, wn = wid >> 2;
    const int m0 = blockIdx.y * 128, n0 = blockIdx.x * 128;
    const int NCH = KTOT / 64;

    auto tileP = [&](int s, int t) -> __nv_bfloat16* { return smb + (s * 4 + t) * 9216; };

    __shared__ float smu[128], srs[128], scol[128], sb1[128];
    if (DEC1 && tid < 128) {
        smu[tid]  = g_stats[(size_t)(m0 + tid) * 2];
        srs[tid]  = g_stats[(size_t)(m0 + tid) * 2 + 1];
        scol[tid] = g_cols[n0 + tid];
        sb1[tid]  = g_bias1[n0 + tid];
    }

    float acc[2][8][4];
    #pragma unroll
    for (int i = 0; i < 2; i++)
        #pragma unroll
        for (int j = 0; j < 8; j++)
            #pragma unroll
            for (int q = 0; q < 4; q++) acc[i][j][q] = 0.0f;

    const __nv_bfloat16* WTh = DEC1 ? g_W1h : g_W2h;
    const __nv_bfloat16* WTl = DEC1 ? g_W1l : g_W2l;

    auto issue = [&](int c) {
        int s = c & 1, k0 = c * 64;
        #pragma unroll
        for (int i = 0; i < 4; i++) {
            int e = tid + i * 256;
            int row = e >> 3, sg = e & 7;
            uint32_t dAh = smem_u32(tileP(s, 0) + row * 72 + sg * 8);
            uint32_t dAl = smem_u32(tileP(s, 1) + row * 72 + sg * 8);
            if (DEC1) {
                if (k0 < Hh) {
                    CP_ASYNC16(dAh, g_spkb + (size_t)(m0 + row) * Hh + k0 + sg * 8);
                } else {
                    CP_ASYNC16(dAh, g_mh + (size_t)(m0 + row) * Hh + (k0 - Hh) + sg * 8);
                    CP_ASYNC16(dAl, g_ml + (size_t)(m0 + row) * Hh + (k0 - Hh) + sg * 8);
                }
            } else {
                CP_ASYNC16(dAh, g_gh + (size_t)(m0 + row) * Hh + k0 + sg * 8);
                CP_ASYNC16(dAl, g_gl + (size_t)(m0 + row) * Hh + k0 + sg * 8);
            }
            CP_ASYNC16(smem_u32(tileP(s, 2) + row * 72 + sg * 8),
                       WTh + (size_t)(n0 + row) * KTOT + k0 + sg * 8);
            CP_ASYNC16(smem_u32(tileP(s, 3) + row * 72 + sg * 8),
                       WTl + (size_t)(n0 + row) * KTOT + k0 + sg * 8);
        }
        CP_COMMIT();
    };

    issue(0);
    if (NCH > 1) issue(1);

    for (int c = 0; c < NCH; c++) {
        const int s = c & 1;
        const int k0 = c * 64;
        const bool exactA = DEC1 && (k0 < Hh);
        if (c + 1 < NCH) CP_WAIT1(); else CP_WAIT0();
        __syncthreads();

        __nv_bfloat16* sAh = tileP(s, 0);
        __nv_bfloat16* sAl = tileP(s, 1);
        __nv_bfloat16* sBh = tileP(s, 2);
        __nv_bfloat16* sBl = tileP(s, 3);

        #pragma unroll
        for (int ks = 0; ks < 4; ks++) {
            uint32_t ah[2][4], al[2][4];
            #pragma unroll
            for (int mt = 0; mt < 2; mt++) {
                int arow = wm * 32 + mt * 16 + (lane & 15);
                int acol = ks * 16 + ((lane >> 4) << 3);
                LDSM4(ah[mt], smem_u32(sAh + arow * 72 + acol));
                if (!exactA) LDSM4(al[mt], smem_u32(sAl + arow * 72 + acol));
            }
            uint32_t bh[8][2], bl[8][2];
            #pragma unroll
            for (int ng = 0; ng < 4; ng++) {
                int brow = wn * 64 + ng * 16 + (lane & 7) + ((lane >> 4) << 3);
                int bcol = ks * 16 + ((lane >> 3) & 1) * 8;
                uint32_t r[4];
                LDSM4(r, smem_u32(sBh + brow * 72 + bcol));
                bh[ng*2][0] = r[0]; bh[ng*2][1] = r[1];
                bh[ng*2+1][0] = r[2]; bh[ng*2+1][1] = r[3];
                LDSM4(r, smem_u32(sBl + brow * 72 + bcol));
                bl[ng*2][0] = r[0]; bl[ng*2][1] = r[1];
                bl[ng*2+1][0] = r[2]; bl[ng*2+1][1] = r[3];
            }
            #pragma unroll
            for (int mt = 0; mt < 2; mt++)
                #pragma unroll
                for (int nt = 0; nt < 8; nt++) {
                    MMA_BF16(acc[mt][nt], ah[mt], bh[nt]);
                    MMA_BF16(acc[mt][nt], ah[mt], bl[nt]);
                    if (!exactA) MMA_BF16(acc[mt][nt], al[mt], bh[nt]);
                }
        }
        __syncthreads();
        if (c + 2 < NCH) issue(c + 2);
    }

    #pragma unroll
    for (int mt = 0; mt < 2; mt++) {
        int lr = wm * 32 + mt * 16 + (lane >> 2);
        #pragma unroll
        for (int nt = 0; nt < 8; nt++) {
            int nl = wn * 64 + nt * 8 + 2 * (lane & 3);
            float* a = acc[mt][nt];
            if (DEC1) {
                float c0 = scol[nl], c1 = scol[nl + 1];
                float b0 = sb1[nl],  b1 = sb1[nl + 1];
                #pragma unroll
                for (int half = 0; half < 2; half++) {
                    int row = lr + half * 8;
                    float mu = smu[row], rs = srs[row];
                    float v0 = gelu_exact(rs * (a[2*half]   - mu * c0) + b0);
                    float v1 = gelu_exact(rs * (a[2*half+1] - mu * c1) + b1);
                    float h0, l0, h1, l1;
                    splitf(v0, h0, l0);
                    splitf(v1, h1, l1);
                    size_t o = (size_t)(m0 + row) * Hh + n0 + nl;
                    *reinterpret_cast<uint32_t*>(g_gh + o) = packbf(h0, h1);
                    *reinterpret_cast<uint32_t*>(g_gl + o) = packbf(l0, l1);
                }
            } else {
                float b0 = biasP[nl], b1 = biasP[nl + 1];
                #pragma unroll
                for (int half = 0; half < 2; half++) {
                    int row = lr + half * 8;
                    float2 v = make_float2(a[2*half] + b0, a[2*half+1] + b1);
                    *reinterpret_cast<float2*>(outP + (size_t)(m0 + row) * Dd + nl) = v;
                }
            }
        }
    }
}

// ---------------- kernel 8: embedding path (tiny) ----------------
__global__ void emb_kernel(const float* __restrict__ ln3g,
                           const float* __restrict__ ln3b,
                           const float* __restrict__ We1,
                           const float* __restrict__ be1,
                           const float* __restrict__ We2,
                           const float* __restrict__ be2,
                           float* __restrict__ out_emb) {
    __shared__ float p[H2];
    __shared__ float garr[Hh];
    __shared__ float sh[32];
    int b = blockIdx.x, tid = threadIdx.x;
    float p0 = g_pooled[b * H2 + tid];
    float p1 = g_pooled[b * H2 + Hh + tid];
    float mu = blockReduceSum(p0 + p1, sh) * (1.0f / H2);
    float d0 = p0 - mu, d1 = p1 - mu;
    float var = blockReduceSum(d0 * d0 + d1 * d1, sh) * (1.0f / H2);
    float rs = rsqrtf(var + EPSc);
    p[tid]      = d0 * rs * ln3g[tid]      + ln3b[tid];
    p[tid + Hh] = d1 * rs * ln3g[tid + Hh] + ln3b[tid + Hh];
    __syncthreads();
    float acc = be1[tid];
    #pragma unroll 8
    for (int k = 0; k < H2; k++) acc += p[k] * We1[k * Hh + tid];
    garr[tid] = gelu_exact(acc);
    __syncthreads();
    if (tid < Ee) {
        float a2 = be2[tid];
        #pragma unroll 8
        for (int j2 = 0; j2 < Hh; j2++) a2 += garr[j2] * We2[j2 * Ee + tid];
        out_emb[b * Ee + tid] = a2;
    }
}

// ---------------- launch ----------------
extern "C" void kernel_launch(void* const* d_in, const int* in_sizes, int n_in,
                              void* d_out, int out_size) {
    const float* x      = (const float*)d_in[0];
    const float* mask   = (const float*)d_in[1];
    const float* ln_g   = (const float*)d_in[2];
    const float* ln_b   = (const float*)d_in[3];
    const float* W_in   = (const float*)d_in[4];
    const float* b_in   = (const float*)d_in[5];
    const float* W_mask = (const float*)d_in[6];
    const float* W_rec  = (const float*)d_in[7];
    const float* ln2_g  = (const float*)d_in[8];
    const float* ln2_b  = (const float*)d_in[9];
    const float* Wd1    = (const float*)d_in[10];
    const float* bd1    = (const float*)d_in[11];
    const float* Wd2    = (const float*)d_in[12];
    const float* bd2    = (const float*)d_in[13];
    const float* ln3_g  = (const float*)d_in[14];
    const float* ln3_b  = (const float*)d_in[15];
    const float* We1    = (const float*)d_in[16];
    const float* be1    = (const float*)d_in[17];
    const float* We2    = (const float*)d_in[18];
    const float* be2    = (const float*)d_in[19];
    float* out = (float*)d_out;

    cudaFuncSetAttribute(scan_kernel,
                         cudaFuncAttributeMaxDynamicSharedMemorySize, SCAN_SMEM);
    cudaFuncSetAttribute(mma_gemm<H2, true>,
                         cudaFuncAttributeMaxDynamicSharedMemorySize, MG_SMEM);
    cudaFuncSetAttribute(mma_gemm<Hh, false>,
                         cudaFuncAttributeMaxDynamicSharedMemorySize, MG_SMEM);

    ln1_kernel<<<BT, 128>>>(x, ln_g, ln_b);
    curin_gemm<<<dim3(Hh / 128, BT / 128), 256>>>(mask, W_in, b_in, W_mask);
    prep_w1<<<Hh, 128>>>(ln2_g, ln2_b, Wd1, bd1);
    prep_w2<<<Dd, Hh>>>(Wd2);
    scan_kernel<<<Bb, Hh, SCAN_SMEM>>>(W_rec);
    rowstats_kernel<<<BT / 8, 256>>>();
    mma_gemm<H2, true><<<dim3(2, BT / 128), 256, MG_SMEM>>>(nullptr, nullptr);
    mma_gemm<Hh, false><<<dim3(1, BT / 128), 256, MG_SMEM>>>(bd2, out);
    emb_kernel<<<Bb, Hh>>>(ln3_g, ln3_b, We1, be1, We2, be2, out + (size_t)BT * Dd);
}

// round 14
// speedup vs baseline: 1.2856x; 1.2856x over previous
#include <cuda_runtime.h>
#include <cuda_bf16.h>
#include <math.h>
#include <stdint.h>

#define Bb     256
#define Tt     512
#define Dd     128
#define Hh     256
#define H2     512
#define Ee     64
#define BT     (Bb * Tt)          // 131072
#define BETAc  0.9f
#define THRc   1.0f
#define RSCALEc 0.25f
#define EPSc   1e-5f

#define WREC_CACHED 104                    // rows cached in smem: 104KB/CTA, 2 CTAs/SM
#define SCAN_SMEM  (WREC_CACHED * Hh * 4)  // 106496 B

// ---------------- scratch (device globals; no allocation allowed) ----------------
__device__ float         g_nx[BT * Dd];       // normalized input (exact R4 bits)
__device__ float         g_curin[BT * Hh];    // input currents
__device__ __nv_bfloat16 g_spkb[BT * Hh];     // spike trace (bf16, exact 0/1)
__device__ __nv_bfloat16 g_mh[BT * Hh];       // membrane hi bf16
__device__ __nv_bfloat16 g_ml[BT * Hh];       // membrane lo bf16
__device__ float         g_stats[BT * 2];     // per-row mu, rstd for LN2
__device__ __nv_bfloat16 g_gh[BT * Hh];       // gmid hi bf16
__device__ __nv_bfloat16 g_gl[BT * Hh];       // gmid lo bf16
__device__ float         g_pooled[Bb * H2];   // [spike mean | last mem (exact fp32)]
__device__ float         g_bias1[Hh];         // bd1 + ln2_b @ Wd1
__device__ float         g_cols[Hh];          // colsum of g*Wd1
__device__ __nv_bfloat16 g_W1h[Hh * H2];      // (g*Wd1)^T hi  [N=256][K=512]
__device__ __nv_bfloat16 g_W1l[Hh * H2];
__device__ __nv_bfloat16 g_W2h[Dd * Hh];      // Wd2^T hi      [N=128][K=256]
__device__ __nv_bfloat16 g_W2l[Dd * Hh];

// ---------------- helpers ----------------
__device__ __forceinline__ float gelu_exact(float v) {
    return 0.5f * v * (1.0f + erff(v * 0.70710678118654752440f));
}
__device__ __forceinline__ uint32_t smem_u32(const void* p) {
    uint32_t a;
    asm("{ .reg .u64 t; cvta.to.shared.u64 t, %1; cvt.u32.u64 %0, t; }" : "=r"(a) : "l"(p));
    return a;
}
__device__ __forceinline__ float blockReduceSum(float v, float* sh) {
    int lane = threadIdx.x & 31, w = threadIdx.x >> 5;
    #pragma unroll
    for (int o = 16; o; o >>= 1) v += __shfl_down_sync(0xffffffffu, v, o);
    if (lane == 0) sh[w] = v;
    __syncthreads();
    int nw = blockDim.x >> 5;
    v = (threadIdx.x < nw) ? sh[threadIdx.x] : 0.0f;
    if (w == 0) {
        #pragma unroll
        for (int o = 16; o; o >>= 1) v += __shfl_down_sync(0xffffffffu, v, o);
        if (lane == 0) sh[0] = v;
    }
    __syncthreads();
    float r = sh[0];
    __syncthreads();
    return r;
}
__device__ __forceinline__ void splitf(float x, float& hi, float& lo) {
    __nv_bfloat16 b = __float2bfloat16(x);
    hi = __bfloat162float(b);
    lo = x - hi;
}
__device__ __forceinline__ uint32_t packbf(float x0, float x1) {
    uint32_t l = __bfloat16_as_ushort(__float2bfloat16(x0));
    uint32_t h = __bfloat16_as_ushort(__float2bfloat16(x1));
    return l | (h << 16);
}

#define LDSM4(r, addr) \
    asm volatile("ldmatrix.sync.aligned.m8n8.x4.shared.b16 {%0,%1,%2,%3}, [%4];" \
        : "=r"((r)[0]), "=r"((r)[1]), "=r"((r)[2]), "=r"((r)[3]) : "r"(addr))

#define MMA_BF16(d, a, b) \
    asm volatile("mma.sync.aligned.m16n8k16.row.col.f32.bf16.bf16.f32 " \
        "{%0,%1,%2,%3}, {%4,%5,%6,%7}, {%8,%9}, {%0,%1,%2,%3};" \
        : "+f"((d)[0]), "+f"((d)[1]), "+f"((d)[2]), "+f"((d)[3]) \
        : "r"((a)[0]), "r"((a)[1]), "r"((a)[2]), "r"((a)[3]), "r"((b)[0]), "r"((b)[1]))

#define CP_ASYNC16(dst, src) \
    asm volatile("cp.async.cg.shared.global [%0], [%1], 16;" :: "r"(dst), "l"(src))
#define CP_COMMIT() asm volatile("cp.async.commit_group;" ::: "memory")
#define CP_WAIT0()  asm volatile("cp.async.wait_group 0;" ::: "memory")
#define CP_WAIT1()  asm volatile("cp.async.wait_group 1;" ::: "memory")

// ---------------- kernel 1: LayerNorm over D=128 (EXACT R4 bits) ----------------
__global__ void ln1_kernel(const float* __restrict__ x,
                           const float* __restrict__ g,
                           const float* __restrict__ b) {
    __shared__ float sh[32];
    int m = blockIdx.x;
    float v = x[m * Dd + threadIdx.x];
    float mu = blockReduceSum(v, sh) * (1.0f / Dd);
    float d = v - mu;
    float var = blockReduceSum(d * d, sh) * (1.0f / Dd);
    g_nx[m * Dd + threadIdx.x] = d * rsqrtf(var + EPSc) * g[threadIdx.x] + b[threadIdx.x];
}

// ---------------- kernel 2: cur_in fp32 SIMT GEMM, pipelined (EXACT R4 FP order) ----------------
// PINNED: curin numerics must stay this exact fp32 bit-path (R6/R7/R12 forensics).
__global__ void __launch_bounds__(256)
curin_gemm(const float* __restrict__ mask,
           const float* __restrict__ W_in,
           const float* __restrict__ b_in,
           const float* __restrict__ W_mask) {
    __shared__ __align__(16) float As[2][16][132];
    __shared__ __align__(16) float Bs[2][16][132];
    int m0 = blockIdx.y * 128, n0 = blockIdx.x * 128;
    int tid = threadIdx.x, ty = tid >> 4, tx = tid & 15;
    float acc[8][8];
    #pragma unroll
    for (int i = 0; i < 8; i++)
        #pragma unroll
        for (int j = 0; j < 8; j++) acc[i][j] = 0.0f;

    float4 rA[2];
    auto loadA = [&](int c, float4* r) {
        const float* A = (c < 8) ? (const float*)g_nx : mask;
        int k0 = (c & 7) * 16;
        #pragma unroll
        for (int rep = 0; rep < 2; rep++) {
            int e = tid + rep * 256;
            int rr = e >> 2, c4 = (e & 3) * 4;
            r[rep] = *reinterpret_cast<const float4*>(A + (size_t)(m0 + rr) * Dd + k0 + c4);
        }
    };
    auto stsA = [&](int s, const float4* r) {
        #pragma unroll
        for (int rep = 0; rep < 2; rep++) {
            int e = tid + rep * 256;
            int rr = e >> 2, c4 = (e & 3) * 4;
            As[s][c4 + 0][rr] = r[rep].x; As[s][c4 + 1][rr] = r[rep].y;
            As[s][c4 + 2][rr] = r[rep].z; As[s][c4 + 3][rr] = r[rep].w;
        }
    };
    auto issueB = [&](int c) {
        const float* Bm = (c < 8) ? W_in : W_mask;
        int k0 = (c & 7) * 16, s = c & 1;
        #pragma unroll
        for (int rep = 0; rep < 2; rep++) {
            int e = tid + rep * 256;
            int rr = e >> 5, cc = (e & 31) * 4;
            CP_ASYNC16(smem_u32(&Bs[s][rr][cc]),
                       Bm + (size_t)(k0 + rr) * Hh + n0 + cc);
        }
        CP_COMMIT();
    };

    loadA(0, rA); issueB(0); stsA(0, rA);
    loadA(1, rA); issueB(1);

    for (int c = 0; c < 16; c++) {
        int s = c & 1;
        if (c + 1 < 16) CP_WAIT1(); else CP_WAIT0();
        __syncthreads();
        #pragma unroll
        for (int k = 0; k < 16; k++) {
            float4 a0 = *reinterpret_cast<const float4*>(&As[s][k][ty * 8]);
            float4 a1 = *reinterpret_cast<const float4*>(&As[s][k][ty * 8 + 4]);
            float4 b0 = *reinterpret_cast<const float4*>(&Bs[s][k][tx * 8]);
            float4 b1 = *reinterpret_cast<const float4*>(&Bs[s][k][tx * 8 + 4]);
            float av[8] = {a0.x, a0.y, a0.z, a0.w, a1.x, a1.y, a1.z, a1.w};
            float bv[8] = {b0.x, b0.y, b0.z, b0.w, b1.x, b1.y, b1.z, b1.w};
            #pragma unroll
            for (int i = 0; i < 8; i++)
                #pragma unroll
                for (int j = 0; j < 8; j++) acc[i][j] += av[i] * bv[j];
        }
        __syncthreads();
        if (c + 1 < 16) stsA(s ^ 1, rA);
        if (c + 2 < 16) { loadA(c + 2, rA); issueB(c + 2); }
    }
    #pragma unroll
    for (int i = 0; i < 8; i++) {
        int m = m0 + ty * 8 + i;
        #pragma unroll
        for (int j = 0; j < 8; j++) {
            int n = n0 + tx * 8 + j;
            g_curin[(size_t)m * Hh + n] = acc[i][j] + b_in[n];
        }
    }
}

// ---------------- kernel 3: scan; partial smem cache (2 CTAs/SM preserved) ----------------
// Add order strictly ascending-j (bit-identical to R9); only load SOURCE varies.
__global__ void __launch_bounds__(256)
scan_kernel(const float* __restrict__ Wrec) {
    extern __shared__ __align__(16) float sW[];   // [WREC_CACHED][Hh]
    __shared__ unsigned char list[Hh];
    __shared__ int warpcnt[8];
    int b = blockIdx.x;
    int h = threadIdx.x;
    int lane = h & 31, w = h >> 5;

    for (int i = h; i < WREC_CACHED * Hh / 4; i += 256)
        reinterpret_cast<float4*>(sW)[i] = reinterpret_cast<const float4*>(Wrec)[i];
    __syncthreads();

    float mem = 0.0f, spksum = 0.0f;
    int prev = 0;
    const float* cbase = g_curin + (size_t)b * Tt * Hh + h;
    __nv_bfloat16* sbase = g_spkb + (size_t)b * Tt * Hh + h;
    __nv_bfloat16* mhb = g_mh + (size_t)b * Tt * Hh + h;
    __nv_bfloat16* mlb = g_ml + (size_t)b * Tt * Hh + h;

    auto wload = [&](int r) -> float {
        return (r < WREC_CACHED) ? sW[r * Hh + h] : __ldg(Wrec + r * Hh + h);
    };

    float cur_next = cbase[0];
    for (int t = 0; t < Tt; t++) {
        unsigned bal = __ballot_sync(0xffffffffu, prev);
        if (lane == 0) warpcnt[w] = __popc(bal);
        __syncthreads();
        int base = 0, ntot = 0;
        #pragma unroll
        for (int i = 0; i < 8; i++) {
            int c = warpcnt[i];
            if (i < w) base += c;
            ntot += c;
        }
        if (prev) list[base + __popc(bal & ((1u << lane) - 1u))] = (unsigned char)h;
        __syncthreads();

        float cin = cur_next;
        if (t + 1 < Tt) cur_next = cbase[(size_t)(t + 1) * Hh];

        float rec = 0.0f;
        int j = 0;
        for (; j + 16 <= ntot; j += 16) {
            float v0  = wload((int)list[j]);
            float v1  = wload((int)list[j + 1]);
            float v2  = wload((int)list[j + 2]);
            float v3  = wload((int)list[j + 3]);
            float v4  = wload((int)list[j + 4]);
            float v5  = wload((int)list[j + 5]);
            float v6  = wload((int)list[j + 6]);
            float v7  = wload((int)list[j + 7]);
            float v8  = wload((int)list[j + 8]);
            float v9  = wload((int)list[j + 9]);
            float v10 = wload((int)list[j + 10]);
            float v11 = wload((int)list[j + 11]);
            float v12 = wload((int)list[j + 12]);
            float v13 = wload((int)list[j + 13]);
            float v14 = wload((int)list[j + 14]);
            float v15 = wload((int)list[j + 15]);
            rec += v0;  rec += v1;  rec += v2;  rec += v3;
            rec += v4;  rec += v5;  rec += v6;  rec += v7;
            rec += v8;  rec += v9;  rec += v10; rec += v11;
            rec += v12; rec += v13; rec += v14; rec += v15;
        }
        for (; j + 8 <= ntot; j += 8) {
            float v0 = wload((int)list[j]);
            float v1 = wload((int)list[j + 1]);
            float v2 = wload((int)list[j + 2]);
            float v3 = wload((int)list[j + 3]);
            float v4 = wload((int)list[j + 4]);
            float v5 = wload((int)list[j + 5]);
            float v6 = wload((int)list[j + 6]);
            float v7 = wload((int)list[j + 7]);
            rec += v0; rec += v1; rec += v2; rec += v3;
            rec += v4; rec += v5; rec += v6; rec += v7;
        }
        for (; j + 4 <= ntot; j += 4) {
            float v0 = wload((int)list[j]);
            float v1 = wload((int)list[j + 1]);
            float v2 = wload((int)list[j + 2]);
            float v3 = wload((int)list[j + 3]);
            rec += v0; rec += v1; rec += v2; rec += v3;
        }
        for (; j < ntot; j++) rec += wload((int)list[j]);

        float cur = cin + rec * RSCALEc;
        mem = BETAc * mem + cur;
        float s = (mem - THRc >= 0.0f) ? 1.0f : 0.0f;
        mem -= s * THRc;
        sbase[(size_t)t * Hh] = __float2bfloat16(s);
        float hi, lo; splitf(mem, hi, lo);
        mhb[(size_t)t * Hh] = __float2bfloat16(hi);
        mlb[(size_t)t * Hh] = __float2bfloat16(lo);
        spksum += s;
        prev = (s != 0.0f);
    }
    g_pooled[b * H2 + h]      = spksum * (1.0f / Tt);
    g_pooled[b * H2 + Hh + h] = mem;
}

// ---------------- kernel 4: per-row LN2 stats, warp per row ----------------
__global__ void rowstats_kernel() {
    int row = blockIdx.x * 8 + (threadIdx.x >> 5);
    int lane = threadIdx.x & 31;
    uint4 a  = *reinterpret_cast<const uint4*>(g_spkb + (size_t)row * Hh + lane * 8);
    uint4 m1 = *reinterpret_cast<const uint4*>(g_mh   + (size_t)row * Hh + lane * 8);
    uint4 m2 = *reinterpret_cast<const uint4*>(g_ml   + (size_t)row * Hh + lane * 8);
    float s = 0.0f, q = 0.0f;
    uint32_t ws[4] = {a.x, a.y, a.z, a.w};
    uint32_t wh[4] = {m1.x, m1.y, m1.z, m1.w};
    uint32_t wl[4] = {m2.x, m2.y, m2.z, m2.w};
    #pragma unroll
    for (int i = 0; i < 4; i++) {
        __nv_bfloat162 p = *reinterpret_cast<__nv_bfloat162*>(&ws[i]);
        float v0 = __low2float(p), v1 = __high2float(p);
        s += v0 + v1;
        q += v0 * v0 + v1 * v1;
        __nv_bfloat162 ph = *reinterpret_cast<__nv_bfloat162*>(&wh[i]);
        __nv_bfloat162 pl = *reinterpret_cast<__nv_bfloat162*>(&wl[i]);
        float c0 = __low2float(ph) + __low2float(pl);
        float c1 = __high2float(ph) + __high2float(pl);
        s += c0 + c1;
        q += c0 * c0 + c1 * c1;
    }
    #pragma unroll
    for (int o = 16; o; o >>= 1) {
        s += __shfl_down_sync(0xffffffffu, s, o);
        q += __shfl_down_sync(0xffffffffu, q, o);
    }
    if (lane == 0) {
        float mu = s * (1.0f / H2);
        float var = q * (1.0f / H2) - mu * mu;
        g_stats[row * 2]     = mu;
        g_stats[row * 2 + 1] = rsqrtf(var + EPSc);
    }
}

// ---------------- prep kernels for decoder weights ----------------
__global__ void prep_w1(const float* __restrict__ ln2g, const float* __restrict__ ln2b,
                        const float* __restrict__ Wd1, const float* __restrict__ bd1) {
    __shared__ float sh[32];
    int n = blockIdx.x, tid = threadIdx.x;
    float cs = 0.0f, bs = 0.0f;
    for (int k = tid; k < H2; k += 128) {
        float wraw = Wd1[k * Hh + n];
        float w = ln2g[k] * wraw;
        float hi, lo; splitf(w, hi, lo);
        g_W1h[n * H2 + k] = __float2bfloat16(hi);
        g_W1l[n * H2 + k] = __float2bfloat16(lo);
        cs += w;
        bs += ln2b[k] * wraw;
    }
    cs = blockReduceSum(cs, sh);
    bs = blockReduceSum(bs, sh);
    if (tid == 0) { g_cols[n] = cs; g_bias1[n] = bd1[n] + bs; }
}
__global__ void prep_w2(const float* __restrict__ Wd2) {
    int n = blockIdx.x, k = threadIdx.x;
    float w = Wd2[k * Dd + n];
    float hi, lo; splitf(w, hi, lo);
    g_W2h[n * Hh + k] = __float2bfloat16(hi);
    g_W2l[n * Hh + k] = __float2bfloat16(lo);
}

// =====================================================================
// mma.sync bf16 split GEMM (decoder), cp.async double-buffered (R9 proven).
// =====================================================================
#define MG_SMEM (2 * 4 * 128 * 72 * 2)   // 147456 bytes

template <int KTOT, bool DEC1>
__global__ void __launch_bounds__(256)
mma_gemm(const float* __restrict__ biasP, float* __restrict__ outP) {
    extern __shared__ __align__(16) __nv_bfloat16 smb[];
    const int tid = threadIdx.x, lane = tid & 31, wid = tid >> 5;
    const int wm = wid & 3, wn = wid >> 2;
    const int m0 = blockIdx.y * 128, n0 = blockIdx.x * 128;
    const int NCH = KTOT / 64;

    auto tileP = [&](int s, int t) -> __nv_bfloat16* { return smb + (s * 4 + t) * 9216; };

    __shared__ float smu[128], srs[128], scol[128], sb1[128];
    if (DEC1 && tid < 128) {
        smu[tid]  = g_stats[(size_t)(m0 + tid) * 2];
        srs[tid]  = g_stats[(size_t)(m0 + tid) * 2 + 1];
        scol[tid] = g_cols[n0 + tid];
        sb1[tid]  = g_bias1[n0 + tid];
    }

    float acc[2][8][4];
    #pragma unroll
    for (int i = 0; i < 2; i++)
        #pragma unroll
        for (int j = 0; j < 8; j++)
            #pragma unroll
            for (int q = 0; q < 4; q++) acc[i][j][q] = 0.0f;

    const __nv_bfloat16* WTh = DEC1 ? g_W1h : g_W2h;
    const __nv_bfloat16* WTl = DEC1 ? g_W1l : g_W2l;

    auto issue = [&](int c) {
        int s = c & 1, k0 = c * 64;
        #pragma unroll
        for (int i = 0; i < 4; i++) {
            int e = tid + i * 256;
            int row = e >> 3, sg = e & 7;
            uint32_t dAh = smem_u32(tileP(s, 0) + row * 72 + sg * 8);
            uint32_t dAl = smem_u32(tileP(s, 1) + row * 72 + sg * 8);
            if (DEC1) {
                if (k0 < Hh) {
                    CP_ASYNC16(dAh, g_spkb + (size_t)(m0 + row) * Hh + k0 + sg * 8);
                } else {
                    CP_ASYNC16(dAh, g_mh + (size_t)(m0 + row) * Hh + (k0 - Hh) + sg * 8);
                    CP_ASYNC16(dAl, g_ml + (size_t)(m0 + row) * Hh + (k0 - Hh) + sg * 8);
                }
            } else {
                CP_ASYNC16(dAh, g_gh + (size_t)(m0 + row) * Hh + k0 + sg * 8);
                CP_ASYNC16(dAl, g_gl + (size_t)(m0 + row) * Hh + k0 + sg * 8);
            }
            CP_ASYNC16(smem_u32(tileP(s, 2) + row * 72 + sg * 8),
                       WTh + (size_t)(n0 + row) * KTOT + k0 + sg * 8);
            CP_ASYNC16(smem_u32(tileP(s, 3) + row * 72 + sg * 8),
                       WTl + (size_t)(n0 + row) * KTOT + k0 + sg * 8);
        }
        CP_COMMIT();
    };

    issue(0);
    if (NCH > 1) issue(1);

    for (int c = 0; c < NCH; c++) {
        const int s = c & 1;
        const int k0 = c * 64;
        const bool exactA = DEC1 && (k0 < Hh);
        if (c + 1 < NCH) CP_WAIT1(); else CP_WAIT0();
        __syncthreads();

        __nv_bfloat16* sAh = tileP(s, 0);
        __nv_bfloat16* sAl = tileP(s, 1);
        __nv_bfloat16* sBh = tileP(s, 2);
        __nv_bfloat16* sBl = tileP(s, 3);

        #pragma unroll
        for (int ks = 0; ks < 4; ks++) {
            uint32_t ah[2][4], al[2][4];
            #pragma unroll
            for (int mt = 0; mt < 2; mt++) {
                int arow = wm * 32 + mt * 16 + (lane & 15);
                int acol = ks * 16 + ((lane >> 4) << 3);
                LDSM4(ah[mt], smem_u32(sAh + arow * 72 + acol));
                if (!exactA) LDSM4(al[mt], smem_u32(sAl + arow * 72 + acol));
            }
            uint32_t bh[8][2], bl[8][2];
            #pragma unroll
            for (int ng = 0; ng < 4; ng++) {
                int brow = wn * 64 + ng * 16 + (lane & 7) + ((lane >> 4) << 3);
                int bcol = ks * 16 + ((lane >> 3) & 1) * 8;
                uint32_t r[4];
                LDSM4(r, smem_u32(sBh + brow * 72 + bcol));
                bh[ng*2][0] = r[0]; bh[ng*2][1] = r[1];
                bh[ng*2+1][0] = r[2]; bh[ng*2+1][1] = r[3];
                LDSM4(r, smem_u32(sBl + brow * 72 + bcol));
                bl[ng*2][0] = r[0]; bl[ng*2][1] = r[1];
                bl[ng*2+1][0] = r[2]; bl[ng*2+1][1] = r[3];
            }
            #pragma unroll
            for (int mt = 0; mt < 2; mt++)
                #pragma unroll
                for (int nt = 0; nt < 8; nt++) {
                    MMA_BF16(acc[mt][nt], ah[mt], bh[nt]);
                    MMA_BF16(acc[mt][nt], ah[mt], bl[nt]);
                    if (!exactA) MMA_BF16(acc[mt][nt], al[mt], bh[nt]);
                }
        }
        __syncthreads();
        if (c + 2 < NCH) issue(c + 2);
    }

    #pragma unroll
    for (int mt = 0; mt < 2; mt++) {
        int lr = wm * 32 + mt * 16 + (lane >> 2);
        #pragma unroll
        for (int nt = 0; nt < 8; nt++) {
            int nl = wn * 64 + nt * 8 + 2 * (lane & 3);
            float* a = acc[mt][nt];
            if (DEC1) {
                float c0 = scol[nl], c1 = scol[nl + 1];
                float b0 = sb1[nl],  b1 = sb1[nl + 1];
                #pragma unroll
                for (int half = 0; half < 2; half++) {
                    int row = lr + half * 8;
                    float mu = smu[row], rs = srs[row];
                    float v0 = gelu_exact(rs * (a[2*half]   - mu * c0) + b0);
                    float v1 = gelu_exact(rs * (a[2*half+1] - mu * c1) + b1);
                    float h0, l0, h1, l1;
                    splitf(v0, h0, l0);
                    splitf(v1, h1, l1);
                    size_t o = (size_t)(m0 + row) * Hh + n0 + nl;
                    *reinterpret_cast<uint32_t*>(g_gh + o) = packbf(h0, h1);
                    *reinterpret_cast<uint32_t*>(g_gl + o) = packbf(l0, l1);
                }
            } else {
                float b0 = biasP[nl], b1 = biasP[nl + 1];
                #pragma unroll
                for (int half = 0; half < 2; half++) {
                    int row = lr + half * 8;
                    float2 v = make_float2(a[2*half] + b0, a[2*half+1] + b1);
                    *reinterpret_cast<float2*>(outP + (size_t)(m0 + row) * Dd + nl) = v;
                }
            }
        }
    }
}

// ---------------- kernel 8: embedding path (tiny) ----------------
__global__ void emb_kernel(const float* __restrict__ ln3g,
                           const float* __restrict__ ln3b,
                           const float* __restrict__ We1,
                           const float* __restrict__ be1,
                           const float* __restrict__ We2,
                           const float* __restrict__ be2,
                           float* __restrict__ out_emb) {
    __shared__ float p[H2];
    __shared__ float garr[Hh];
    __shared__ float sh[32];
    int b = blockIdx.x, tid = threadIdx.x;
    float p0 = g_pooled[b * H2 + tid];
    float p1 = g_pooled[b * H2 + Hh + tid];
    float mu = blockReduceSum(p0 + p1, sh) * (1.0f / H2);
    float d0 = p0 - mu, d1 = p1 - mu;
    float var = blockReduceSum(d0 * d0 + d1 * d1, sh) * (1.0f / H2);
    float rs = rsqrtf(var + EPSc);
    p[tid]      = d0 * rs * ln3g[tid]      + ln3b[tid];
    p[tid + Hh] = d1 * rs * ln3g[tid + Hh] + ln3b[tid + Hh];
    __syncthreads();
    float acc = be1[tid];
    #pragma unroll 8
    for (int k = 0; k < H2; k++) acc += p[k] * We1[k * Hh + tid];
    garr[tid] = gelu_exact(acc);
    __syncthreads();
    if (tid < Ee) {
        float a2 = be2[tid];
        #pragma unroll 8
        for (int j2 = 0; j2 < Hh; j2++) a2 += garr[j2] * We2[j2 * Ee + tid];
        out_emb[b * Ee + tid] = a2;
    }
}

// ---------------- launch ----------------
extern "C" void kernel_launch(void* const* d_in, const int* in_sizes, int n_in,
                              void* d_out, int out_size) {
    const float* x      = (const float*)d_in[0];
    const float* mask   = (const float*)d_in[1];
    const float* ln_g   = (const float*)d_in[2];
    const float* ln_b   = (const float*)d_in[3];
    const float* W_in   = (const float*)d_in[4];
    const float* b_in   = (const float*)d_in[5];
    const float* W_mask = (const float*)d_in[6];
    const float* W_rec  = (const float*)d_in[7];
    const float* ln2_g  = (const float*)d_in[8];
    const float* ln2_b  = (const float*)d_in[9];
    const float* Wd1    = (const float*)d_in[10];
    const float* bd1    = (const float*)d_in[11];
    const float* Wd2    = (const float*)d_in[12];
    const float* bd2    = (const float*)d_in[13];
    const float* ln3_g  = (const float*)d_in[14];
    const float* ln3_b  = (const float*)d_in[15];
    const float* We1    = (const float*)d_in[16];
    const float* be1    = (const float*)d_in[17];
    const float* We2    = (const float*)d_in[18];
    const float* be2    = (const float*)d_in[19];
    float* out = (float*)d_out;

    cudaFuncSetAttribute(scan_kernel,
                         cudaFuncAttributeMaxDynamicSharedMemorySize, SCAN_SMEM);
    cudaFuncSetAttribute(mma_gemm<H2, true>,
                         cudaFuncAttributeMaxDynamicSharedMemorySize, MG_SMEM);
    cudaFuncSetAttribute(mma_gemm<Hh, false>,
                         cudaFuncAttributeMaxDynamicSharedMemorySize, MG_SMEM);

    ln1_kernel<<<BT, 128>>>(x, ln_g, ln_b);
    curin_gemm<<<dim3(Hh / 128, BT / 128), 256>>>(mask, W_in, b_in, W_mask);
    prep_w1<<<Hh, 128>>>(ln2_g, ln2_b, Wd1, bd1);
    prep_w2<<<Dd, Hh>>>(Wd2);
    scan_kernel<<<Bb, Hh, SCAN_SMEM>>>(W_rec);
    rowstats_kernel<<<BT / 8, 256>>>();
    mma_gemm<H2, true><<<dim3(2, BT / 128), 256, MG_SMEM>>>(nullptr, nullptr);
    mma_gemm<Hh, false><<<dim3(1, BT / 128), 256, MG_SMEM>>>(bd2, out);
    emb_kernel<<<Bb, Hh>>>(ln3_g, ln3_b, We1, be1, We2, be2, out + (size_t)BT * Dd);
}

// round 15
// speedup vs baseline: 1.4698x; 1.1433x over previous
#include <cuda_runtime.h>
#include <cuda_bf16.h>
#include <math.h>
#include <stdint.h>

#define Bb     256
#define Tt     512
#define Dd     128
#define Hh     256
#define H2     512
#define Ee     64
#define BT     (Bb * Tt)          // 131072
#define BETAc  0.9f
#define THRc   1.0f
#define RSCALEc 0.25f
#define EPSc   1e-5f

// ---------------- scratch (device globals; no allocation allowed) ----------------
__device__ float         g_nx[BT * Dd];       // normalized input (exact R4 bits)
__device__ float         g_curin[BT * Hh];    // input currents
__device__ __nv_bfloat16 g_spkb[BT * Hh];     // spike trace (bf16, exact 0/1)
__device__ __nv_bfloat16 g_mh[BT * Hh];       // membrane hi bf16
__device__ __nv_bfloat16 g_ml[BT * Hh];       // membrane lo bf16
__device__ float         g_stats[BT * 2];     // per-row mu, rstd for LN2
__device__ __nv_bfloat16 g_gh[BT * Hh];       // gmid hi bf16
__device__ __nv_bfloat16 g_gl[BT * Hh];       // gmid lo bf16
__device__ float         g_pooled[Bb * H2];   // [spike mean | last mem (exact fp32)]
__device__ float         g_bias1[Hh];         // bd1 + ln2_b @ Wd1
__device__ float         g_cols[Hh];          // colsum of g*Wd1
__device__ __nv_bfloat16 g_W1h[Hh * H2];      // (g*Wd1)^T hi  [N=256][K=512]
__device__ __nv_bfloat16 g_W1l[Hh * H2];
__device__ __nv_bfloat16 g_W2h[Dd * Hh];      // Wd2^T hi      [N=128][K=256]
__device__ __nv_bfloat16 g_W2l[Dd * Hh];

// ---------------- helpers ----------------
__device__ __forceinline__ float gelu_exact(float v) {
    return 0.5f * v * (1.0f + erff(v * 0.70710678118654752440f));
}
__device__ __forceinline__ uint32_t smem_u32(const void* p) {
    uint32_t a;
    asm("{ .reg .u64 t; cvta.to.shared.u64 t, %1; cvt.u32.u64 %0, t; }" : "=r"(a) : "l"(p));
    return a;
}
__device__ __forceinline__ float blockReduceSum(float v, float* sh) {
    int lane = threadIdx.x & 31, w = threadIdx.x >> 5;
    #pragma unroll
    for (int o = 16; o; o >>= 1) v += __shfl_down_sync(0xffffffffu, v, o);
    if (lane == 0) sh[w] = v;
    __syncthreads();
    int nw = blockDim.x >> 5;
    v = (threadIdx.x < nw) ? sh[threadIdx.x] : 0.0f;
    if (w == 0) {
        #pragma unroll
        for (int o = 16; o; o >>= 1) v += __shfl_down_sync(0xffffffffu, v, o);
        if (lane == 0) sh[0] = v;
    }
    __syncthreads();
    float r = sh[0];
    __syncthreads();
    return r;
}
__device__ __forceinline__ void splitf(float x, float& hi, float& lo) {
    __nv_bfloat16 b = __float2bfloat16(x);
    hi = __bfloat162float(b);
    lo = x - hi;
}
__device__ __forceinline__ uint32_t packbf(float x0, float x1) {
    uint32_t l = __bfloat16_as_ushort(__float2bfloat16(x0));
    uint32_t h = __bfloat16_as_ushort(__float2bfloat16(x1));
    return l | (h << 16);
}

#define LDSM4(r, addr) \
    asm volatile("ldmatrix.sync.aligned.m8n8.x4.shared.b16 {%0,%1,%2,%3}, [%4];" \
        : "=r"((r)[0]), "=r"((r)[1]), "=r"((r)[2]), "=r"((r)[3]) : "r"(addr))

#define MMA_BF16(d, a, b) \
    asm volatile("mma.sync.aligned.m16n8k16.row.col.f32.bf16.bf16.f32 " \
        "{%0,%1,%2,%3}, {%4,%5,%6,%7}, {%8,%9}, {%0,%1,%2,%3};" \
        : "+f"((d)[0]), "+f"((d)[1]), "+f"((d)[2]), "+f"((d)[3]) \
        : "r"((a)[0]), "r"((a)[1]), "r"((a)[2]), "r"((a)[3]), "r"((b)[0]), "r"((b)[1]))

#define CP_ASYNC16(dst, src) \
    asm volatile("cp.async.cg.shared.global [%0], [%1], 16;" :: "r"(dst), "l"(src))
#define CP_COMMIT() asm volatile("cp.async.commit_group;" ::: "memory")
#define CP_WAIT0()  asm volatile("cp.async.wait_group 0;" ::: "memory")
#define CP_WAIT1()  asm volatile("cp.async.wait_group 1;" ::: "memory")

// ---------------- kernel 1: LayerNorm over D=128 (EXACT R4 bits) ----------------
__global__ void ln1_kernel(const float* __restrict__ x,
                           const float* __restrict__ g,
                           const float* __restrict__ b) {
    __shared__ float sh[32];
    int m = blockIdx.x;
    float v = x[m * Dd + threadIdx.x];
    float mu = blockReduceSum(v, sh) * (1.0f / Dd);
    float d = v - mu;
    float var = blockReduceSum(d * d, sh) * (1.0f / Dd);
    g_nx[m * Dd + threadIdx.x] = d * rsqrtf(var + EPSc) * g[threadIdx.x] + b[threadIdx.x];
}

// ---------------- kernel 2: cur_in fp32 SIMT GEMM, pipelined (EXACT R4 FP order) ----------------
// PINNED: curin numerics must stay this exact fp32 bit-path (R6/R7/R12 forensics).
__global__ void __launch_bounds__(256)
curin_gemm(const float* __restrict__ mask,
           const float* __restrict__ W_in,
           const float* __restrict__ b_in,
           const float* __restrict__ W_mask) {
    __shared__ __align__(16) float As[2][16][132];
    __shared__ __align__(16) float Bs[2][16][132];
    int m0 = blockIdx.y * 128, n0 = blockIdx.x * 128;
    int tid = threadIdx.x, ty = tid >> 4, tx = tid & 15;
    float acc[8][8];
    #pragma unroll
    for (int i = 0; i < 8; i++)
        #pragma unroll
        for (int j = 0; j < 8; j++) acc[i][j] = 0.0f;

    float4 rA[2];
    auto loadA = [&](int c, float4* r) {
        const float* A = (c < 8) ? (const float*)g_nx : mask;
        int k0 = (c & 7) * 16;
        #pragma unroll
        for (int rep = 0; rep < 2; rep++) {
            int e = tid + rep * 256;
            int rr = e >> 2, c4 = (e & 3) * 4;
            r[rep] = *reinterpret_cast<const float4*>(A + (size_t)(m0 + rr) * Dd + k0 + c4);
        }
    };
    auto stsA = [&](int s, const float4* r) {
        #pragma unroll
        for (int rep = 0; rep < 2; rep++) {
            int e = tid + rep * 256;
            int rr = e >> 2, c4 = (e & 3) * 4;
            As[s][c4 + 0][rr] = r[rep].x; As[s][c4 + 1][rr] = r[rep].y;
            As[s][c4 + 2][rr] = r[rep].z; As[s][c4 + 3][rr] = r[rep].w;
        }
    };
    auto issueB = [&](int c) {
        const float* Bm = (c < 8) ? W_in : W_mask;
        int k0 = (c & 7) * 16, s = c & 1;
        #pragma unroll
        for (int rep = 0; rep < 2; rep++) {
            int e = tid + rep * 256;
            int rr = e >> 5, cc = (e & 31) * 4;
            CP_ASYNC16(smem_u32(&Bs[s][rr][cc]),
                       Bm + (size_t)(k0 + rr) * Hh + n0 + cc);
        }
        CP_COMMIT();
    };

    loadA(0, rA); issueB(0); stsA(0, rA);
    loadA(1, rA); issueB(1);

    for (int c = 0; c < 16; c++) {
        int s = c & 1;
        if (c + 1 < 16) CP_WAIT1(); else CP_WAIT0();
        __syncthreads();
        #pragma unroll
        for (int k = 0; k < 16; k++) {
            float4 a0 = *reinterpret_cast<const float4*>(&As[s][k][ty * 8]);
            float4 a1 = *reinterpret_cast<const float4*>(&As[s][k][ty * 8 + 4]);
            float4 b0 = *reinterpret_cast<const float4*>(&Bs[s][k][tx * 8]);
            float4 b1 = *reinterpret_cast<const float4*>(&Bs[s][k][tx * 8 + 4]);
            float av[8] = {a0.x, a0.y, a0.z, a0.w, a1.x, a1.y, a1.z, a1.w};
            float bv[8] = {b0.x, b0.y, b0.z, b0.w, b1.x, b1.y, b1.z, b1.w};
            #pragma unroll
            for (int i = 0; i < 8; i++)
                #pragma unroll
                for (int j = 0; j < 8; j++) acc[i][j] += av[i] * bv[j];
        }
        __syncthreads();
        if (c + 1 < 16) stsA(s ^ 1, rA);
        if (c + 2 < 16) { loadA(c + 2, rA); issueB(c + 2); }
    }
    #pragma unroll
    for (int i = 0; i < 8; i++) {
        int m = m0 + ty * 8 + i;
        #pragma unroll
        for (int j = 0; j < 8; j++) {
            int n = n0 + tx * 8 + j;
            g_curin[(size_t)m * Hh + n] = acc[i][j] + b_in[n];
        }
    }
}

// ---------------- kernel 3: scan; 32-wide predicated single-round gather ----------------
// Add order strictly ascending-j; padding adds exact +0.0f -> bit-identical to R9.
__global__ void __launch_bounds__(256)
scan_kernel(const float* __restrict__ Wrec) {
    __shared__ unsigned char list[Hh];
    __shared__ int warpcnt[8];
    int b = blockIdx.x;
    int h = threadIdx.x;
    int lane = h & 31, w = h >> 5;
    float mem = 0.0f, spksum = 0.0f;
    int prev = 0;
    const float* cbase = g_curin + (size_t)b * Tt * Hh + h;
    __nv_bfloat16* sbase = g_spkb + (size_t)b * Tt * Hh + h;
    __nv_bfloat16* mhb = g_mh + (size_t)b * Tt * Hh + h;
    __nv_bfloat16* mlb = g_ml + (size_t)b * Tt * Hh + h;

    float cur_next = cbase[0];
    for (int t = 0; t < Tt; t++) {
        unsigned bal = __ballot_sync(0xffffffffu, prev);
        if (lane == 0) warpcnt[w] = __popc(bal);
        __syncthreads();
        int base = 0, ntot = 0;
        #pragma unroll
        for (int i = 0; i < 8; i++) {
            int c = warpcnt[i];
            if (i < w) base += c;
            ntot += c;
        }
        if (prev) list[base + __popc(bal & ((1u << lane) - 1u))] = (unsigned char)h;
        __syncthreads();

        float cin = cur_next;
        if (t + 1 < Tt) cur_next = cbase[(size_t)(t + 1) * Hh];

        float rec = 0.0f;
        for (int j = 0; j < ntot; j += 32) {
            float v[32];
            #pragma unroll
            for (int u = 0; u < 32; u++) {
                int jj = j + u;
                v[u] = (jj < ntot) ? __ldg(Wrec + (int)list[jj] * Hh + h) : 0.0f;
            }
            #pragma unroll
            for (int u = 0; u < 32; u++) rec += v[u];
        }

        float cur = cin + rec * RSCALEc;
        mem = BETAc * mem + cur;
        float s = (mem - THRc >= 0.0f) ? 1.0f : 0.0f;
        mem -= s * THRc;
        sbase[(size_t)t * Hh] = __float2bfloat16(s);
        float hi, lo; splitf(mem, hi, lo);
        mhb[(size_t)t * Hh] = __float2bfloat16(hi);
        mlb[(size_t)t * Hh] = __float2bfloat16(lo);
        spksum += s;
        prev = (s != 0.0f);
    }
    g_pooled[b * H2 + h]      = spksum * (1.0f / Tt);
    g_pooled[b * H2 + Hh + h] = mem;   // exact fp32 last membrane
}

// ---------------- kernel 4: per-row LN2 stats, warp per row ----------------
__global__ void rowstats_kernel() {
    int row = blockIdx.x * 8 + (threadIdx.x >> 5);
    int lane = threadIdx.x & 31;
    uint4 a  = *reinterpret_cast<const uint4*>(g_spkb + (size_t)row * Hh + lane * 8);
    uint4 m1 = *reinterpret_cast<const uint4*>(g_mh   + (size_t)row * Hh + lane * 8);
    uint4 m2 = *reinterpret_cast<const uint4*>(g_ml   + (size_t)row * Hh + lane * 8);
    float s = 0.0f, q = 0.0f;
    uint32_t ws[4] = {a.x, a.y, a.z, a.w};
    uint32_t wh[4] = {m1.x, m1.y, m1.z, m1.w};
    uint32_t wl[4] = {m2.x, m2.y, m2.z, m2.w};
    #pragma unroll
    for (int i = 0; i < 4; i++) {
        __nv_bfloat162 p = *reinterpret_cast<__nv_bfloat162*>(&ws[i]);
        float v0 = __low2float(p), v1 = __high2float(p);
        s += v0 + v1;
        q += v0 * v0 + v1 * v1;
        __nv_bfloat162 ph = *reinterpret_cast<__nv_bfloat162*>(&wh[i]);
        __nv_bfloat162 pl = *reinterpret_cast<__nv_bfloat162*>(&wl[i]);
        float c0 = __low2float(ph) + __low2float(pl);
        float c1 = __high2float(ph) + __high2float(pl);
        s += c0 + c1;
        q += c0 * c0 + c1 * c1;
    }
    #pragma unroll
    for (int o = 16; o; o >>= 1) {
        s += __shfl_down_sync(0xffffffffu, s, o);
        q += __shfl_down_sync(0xffffffffu, q, o);
    }
    if (lane == 0) {
        float mu = s * (1.0f / H2);
        float var = q * (1.0f / H2) - mu * mu;
        g_stats[row * 2]     = mu;
        g_stats[row * 2 + 1] = rsqrtf(var + EPSc);
    }
}

// ---------------- prep kernels for decoder weights ----------------
__global__ void prep_w1(const float* __restrict__ ln2g, const float* __restrict__ ln2b,
                        const float* __restrict__ Wd1, const float* __restrict__ bd1) {
    __shared__ float sh[32];
    int n = blockIdx.x, tid = threadIdx.x;
    float cs = 0.0f, bs = 0.0f;
    for (int k = tid; k < H2; k += 128) {
        float wraw = Wd1[k * Hh + n];
        float w = ln2g[k] * wraw;
        float hi, lo; splitf(w, hi, lo);
        g_W1h[n * H2 + k] = __float2bfloat16(hi);
        g_W1l[n * H2 + k] = __float2bfloat16(lo);
        cs += w;
        bs += ln2b[k] * wraw;
    }
    cs = blockReduceSum(cs, sh);
    bs = blockReduceSum(bs, sh);
    if (tid == 0) { g_cols[n] = cs; g_bias1[n] = bd1[n] + bs; }
}
__global__ void prep_w2(const float* __restrict__ Wd2) {
    int n = blockIdx.x, k = threadIdx.x;
    float w = Wd2[k * Dd + n];
    float hi, lo; splitf(w, hi, lo);
    g_W2h[n * Hh + k] = __float2bfloat16(hi);
    g_W2l[n * Hh + k] = __float2bfloat16(lo);
}

// =====================================================================
// mma.sync bf16 split GEMM (decoder), cp.async double-buffered (R9 proven).
// =====================================================================
#define MG_SMEM (2 * 4 * 128 * 72 * 2)   // 147456 bytes

template <int KTOT, bool DEC1>
__global__ void __launch_bounds__(256)
mma_gemm(const float* __restrict__ biasP, float* __restrict__ outP) {
    extern __shared__ __align__(16) __nv_bfloat16 smb[];
    const int tid = threadIdx.x, lane = tid & 31, wid = tid >> 5;
    const int wm = wid & 3, wn = wid >> 2;
    const int m0 = blockIdx.y * 128, n0 = blockIdx.x * 128;
    const int NCH = KTOT / 64;

    auto tileP = [&](int s, int t) -> __nv_bfloat16* { return smb + (s * 4 + t) * 9216; };

    __shared__ float smu[128], srs[128], scol[128], sb1[128];
    if (DEC1 && tid < 128) {
        smu[tid]  = g_stats[(size_t)(m0 + tid) * 2];
        srs[tid]  = g_stats[(size_t)(m0 + tid) * 2 + 1];
        scol[tid] = g_cols[n0 + tid];
        sb1[tid]  = g_bias1[n0 + tid];
    }

    float acc[2][8][4];
    #pragma unroll
    for (int i = 0; i < 2; i++)
        #pragma unroll
        for (int j = 0; j < 8; j++)
            #pragma unroll
            for (int q = 0; q < 4; q++) acc[i][j][q] = 0.0f;

    const __nv_bfloat16* WTh = DEC1 ? g_W1h : g_W2h;
    const __nv_bfloat16* WTl = DEC1 ? g_W1l : g_W2l;

    auto issue = [&](int c) {
        int s = c & 1, k0 = c * 64;
        #pragma unroll
        for (int i = 0; i < 4; i++) {
            int e = tid + i * 256;
            int row = e >> 3, sg = e & 7;
            uint32_t dAh = smem_u32(tileP(s, 0) + row * 72 + sg * 8);
            uint32_t dAl = smem_u32(tileP(s, 1) + row * 72 + sg * 8);
            if (DEC1) {
                if (k0 < Hh) {
                    CP_ASYNC16(dAh, g_spkb + (size_t)(m0 + row) * Hh + k0 + sg * 8);
                } else {
                    CP_ASYNC16(dAh, g_mh + (size_t)(m0 + row) * Hh + (k0 - Hh) + sg * 8);
                    CP_ASYNC16(dAl, g_ml + (size_t)(m0 + row) * Hh + (k0 - Hh) + sg * 8);
                }
            } else {
                CP_ASYNC16(dAh, g_gh + (size_t)(m0 + row) * Hh + k0 + sg * 8);
                CP_ASYNC16(dAl, g_gl + (size_t)(m0 + row) * Hh + k0 + sg * 8);
            }
            CP_ASYNC16(smem_u32(tileP(s, 2) + row * 72 + sg * 8),
                       WTh + (size_t)(n0 + row) * KTOT + k0 + sg * 8);
            CP_ASYNC16(smem_u32(tileP(s, 3) + row * 72 + sg * 8),
                       WTl + (size_t)(n0 + row) * KTOT + k0 + sg * 8);
        }
        CP_COMMIT();
    };

    issue(0);
    if (NCH > 1) issue(1);

    for (int c = 0; c < NCH; c++) {
        const int s = c & 1;
        const int k0 = c * 64;
        const bool exactA = DEC1 && (k0 < Hh);
        if (c + 1 < NCH) CP_WAIT1(); else CP_WAIT0();
        __syncthreads();

        __nv_bfloat16* sAh = tileP(s, 0);
        __nv_bfloat16* sAl = tileP(s, 1);
        __nv_bfloat16* sBh = tileP(s, 2);
        __nv_bfloat16* sBl = tileP(s, 3);

        #pragma unroll
        for (int ks = 0; ks < 4; ks++) {
            uint32_t ah[2][4], al[2][4];
            #pragma unroll
            for (int mt = 0; mt < 2; mt++) {
                int arow = wm * 32 + mt * 16 + (lane & 15);
                int acol = ks * 16 + ((lane >> 4) << 3);
                LDSM4(ah[mt], smem_u32(sAh + arow * 72 + acol));
                if (!exactA) LDSM4(al[mt], smem_u32(sAl + arow * 72 + acol));
            }
            uint32_t bh[8][2], bl[8][2];
            #pragma unroll
            for (int ng = 0; ng < 4; ng++) {
                int brow = wn * 64 + ng * 16 + (lane & 7) + ((lane >> 4) << 3);
                int bcol = ks * 16 + ((lane >> 3) & 1) * 8;
                uint32_t r[4];
                LDSM4(r, smem_u32(sBh + brow * 72 + bcol));
                bh[ng*2][0] = r[0]; bh[ng*2][1] = r[1];
                bh[ng*2+1][0] = r[2]; bh[ng*2+1][1] = r[3];
                LDSM4(r, smem_u32(sBl + brow * 72 + bcol));
                bl[ng*2][0] = r[0]; bl[ng*2][1] = r[1];
                bl[ng*2+1][0] = r[2]; bl[ng*2+1][1] = r[3];
            }
            #pragma unroll
            for (int mt = 0; mt < 2; mt++)
                #pragma unroll
                for (int nt = 0; nt < 8; nt++) {
                    MMA_BF16(acc[mt][nt], ah[mt], bh[nt]);
                    MMA_BF16(acc[mt][nt], ah[mt], bl[nt]);
                    if (!exactA) MMA_BF16(acc[mt][nt], al[mt], bh[nt]);
                }
        }
        __syncthreads();
        if (c + 2 < NCH) issue(c + 2);
    }

    #pragma unroll
    for (int mt = 0; mt < 2; mt++) {
        int lr = wm * 32 + mt * 16 + (lane >> 2);
        #pragma unroll
        for (int nt = 0; nt < 8; nt++) {
            int nl = wn * 64 + nt * 8 + 2 * (lane & 3);
            float* a = acc[mt][nt];
            if (DEC1) {
                float c0 = scol[nl], c1 = scol[nl + 1];
                float b0 = sb1[nl],  b1 = sb1[nl + 1];
                #pragma unroll
                for (int half = 0; half < 2; half++) {
                    int row = lr + half * 8;
                    float mu = smu[row], rs = srs[row];
                    float v0 = gelu_exact(rs * (a[2*half]   - mu * c0) + b0);
                    float v1 = gelu_exact(rs * (a[2*half+1] - mu * c1) + b1);
                    float h0, l0, h1, l1;
                    splitf(v0, h0, l0);
                    splitf(v1, h1, l1);
                    size_t o = (size_t)(m0 + row) * Hh + n0 + nl;
                    *reinterpret_cast<uint32_t*>(g_gh + o) = packbf(h0, h1);
                    *reinterpret_cast<uint32_t*>(g_gl + o) = packbf(l0, l1);
                }
            } else {
                float b0 = biasP[nl], b1 = biasP[nl + 1];
                #pragma unroll
                for (int half = 0; half < 2; half++) {
                    int row = lr + half * 8;
                    float2 v = make_float2(a[2*half] + b0, a[2*half+1] + b1);
                    *reinterpret_cast<float2*>(outP + (size_t)(m0 + row) * Dd + nl) = v;
                }
            }
        }
    }
}

// ---------------- kernel 8: embedding path (tiny) ----------------
__global__ void emb_kernel(const float* __restrict__ ln3g,
                           const float* __restrict__ ln3b,
                           const float* __restrict__ We1,
                           const float* __restrict__ be1,
                           const float* __restrict__ We2,
                           const float* __restrict__ be2,
                           float* __restrict__ out_emb) {
    __shared__ float p[H2];
    __shared__ float garr[Hh];
    __shared__ float sh[32];
    int b = blockIdx.x, tid = threadIdx.x;
    float p0 = g_pooled[b * H2 + tid];
    float p1 = g_pooled[b * H2 + Hh + tid];
    float mu = blockReduceSum(p0 + p1, sh) * (1.0f / H2);
    float d0 = p0 - mu, d1 = p1 - mu;
    float var = blockReduceSum(d0 * d0 + d1 * d1, sh) * (1.0f / H2);
    float rs = rsqrtf(var + EPSc);
    p[tid]      = d0 * rs * ln3g[tid]      + ln3b[tid];
    p[tid + Hh] = d1 * rs * ln3g[tid + Hh] + ln3b[tid + Hh];
    __syncthreads();
    float acc = be1[tid];
    #pragma unroll 8
    for (int k = 0; k < H2; k++) acc += p[k] * We1[k * Hh + tid];
    garr[tid] = gelu_exact(acc);
    __syncthreads();
    if (tid < Ee) {
        float a2 = be2[tid];
        #pragma unroll 8
        for (int j2 = 0; j2 < Hh; j2++) a2 += garr[j2] * We2[j2 * Ee + tid];
        out_emb[b * Ee + tid] = a2;
    }
}

// ---------------- launch ----------------
extern "C" void kernel_launch(void* const* d_in, const int* in_sizes, int n_in,
                              void* d_out, int out_size) {
    const float* x      = (const float*)d_in[0];
    const float* mask   = (const float*)d_in[1];
    const float* ln_g   = (const float*)d_in[2];
    const float* ln_b   = (const float*)d_in[3];
    const float* W_in   = (const float*)d_in[4];
    const float* b_in   = (const float*)d_in[5];
    const float* W_mask = (const float*)d_in[6];
    const float* W_rec  = (const float*)d_in[7];
    const float* ln2_g  = (const float*)d_in[8];
    const float* ln2_b  = (const float*)d_in[9];
    const float* Wd1    = (const float*)d_in[10];
    const float* bd1    = (const float*)d_in[11];
    const float* Wd2    = (const float*)d_in[12];
    const float* bd2    = (const float*)d_in[13];
    const float* ln3_g  = (const float*)d_in[14];
    const float* ln3_b  = (const float*)d_in[15];
    const float* We1    = (const float*)d_in[16];
    const float* be1    = (const float*)d_in[17];
    const float* We2    = (const float*)d_in[18];
    const float* be2    = (const float*)d_in[19];
    float* out = (float*)d_out;

    cudaFuncSetAttribute(mma_gemm<H2, true>,
                         cudaFuncAttributeMaxDynamicSharedMemorySize, MG_SMEM);
    cudaFuncSetAttribute(mma_gemm<Hh, false>,
                         cudaFuncAttributeMaxDynamicSharedMemorySize, MG_SMEM);

    ln1_kernel<<<BT, 128>>>(x, ln_g, ln_b);
    curin_gemm<<<dim3(Hh / 128, BT / 128), 256>>>(mask, W_in, b_in, W_mask);
    prep_w1<<<Hh, 128>>>(ln2_g, ln2_b, Wd1, bd1);
    prep_w2<<<Dd, Hh>>>(Wd2);
    scan_kernel<<<Bb, Hh>>>(W_rec);
    rowstats_kernel<<<BT / 8, 256>>>();
    mma_gemm<H2, true><<<dim3(2, BT / 128), 256, MG_SMEM>>>(nullptr, nullptr);
    mma_gemm<Hh, false><<<dim3(1, BT / 128), 256, MG_SMEM>>>(bd2, out);
    emb_kernel<<<Bb, Hh>>>(ln3_g, ln3_b, We1, be1, We2, be2, out + (size_t)BT * Dd);
}